// round 5
// baseline (speedup 1.0000x reference)
#include <cuda_runtime.h>
#include <cuda_bf16.h>
#include <math.h>

// ---------------------------------------------------------------------------
// DiscriptorMatchLoss — sparse cosine matching loss via bucket spatial hash.
//   mask[i,j,n,m] = ||denorm(ps[i,n]) - denorm(pd[i,j,m])||^2 <= 64
//   out = sum_mask (1 - cos(f[j,n], f[i,m])) / max(count,1)
// K1: chip-wide bucket-bin of all B*B*N dst points (fixed-cap cells).
// K2: chip-wide match (1 thread per (i,j,n)) -> compact hit-pair list.
// K3: cosine dots with inline norms (8 lanes/pair, 4 pairs/warp), block
//     reduction, distributed state reset, last-block finalize. No K4.
// ---------------------------------------------------------------------------

#define MAXC      2048          // max cells per (i,j) pair
#define MAXIJ     16
#define CAP       32            // bucket capacity (lambda~1.7 => safe)
#define MAX_PAIRS (1 << 20)
#define RAD       8.0f
#define RAD2      64.0f
#define DOT_GRID  2048

__device__ double   g_sum;                      // reset by last k_dot block
__device__ int      g_npairs;                   // reset by last k_dot block
__device__ unsigned g_done;                     // arrival counter
__device__ int      g_ccnt[MAXIJ * MAXC];       // bucket counts (reset in k_dot)
__device__ float2   g_cpts[MAXIJ * MAXC * CAP];
__device__ int      g_cidx[MAXIJ * MAXC * CAP];
__device__ unsigned g_pairs[MAX_PAIRS];

__device__ __forceinline__ void grid_shape(int W, int H, int& s, int& ncx, int& ncy) {
    s = 4;
    ncx = ((W - 1) >> s) + 1; ncy = ((H - 1) >> s) + 1;
    while (ncx * ncy > MAXC) { s++; ncx = ((W - 1) >> s) + 1; ncy = ((H - 1) >> s) + 1; }
}

// ---------------- K1: bucket-bin dst points --------------------------------
__global__ void __launch_bounds__(256)
k_bin(const float* __restrict__ pd,
      const int* __restrict__ hp,
      const int* __restrict__ wp,
      int B, int N) {
    int t = blockIdx.x * 256 + threadIdx.x;
    int total = B * B * N;
    if (t >= total) return;
    int ij = t / N;
    int W = wp[0], H = hp[0];
    int s, ncx, ncy; grid_shape(W, H, s, ncx, ncy);
    float inv_c = 1.0f / (float)(1 << s);
    float sx = 0.5f * (float)(W - 1), sy = 0.5f * (float)(H - 1);

    float2 q = ((const float2*)pd)[t];
    float x = (q.x + 1.0f) * sx, y = (q.y + 1.0f) * sy;
    int cx = min(ncx - 1, max(0, (int)(x * inv_c)));
    int cy = min(ncy - 1, max(0, (int)(y * inv_c)));
    int cell = ij * MAXC + cy * ncx + cx;
    int slot = atomicAdd(&g_ccnt[cell], 1);
    if (slot < CAP) {
        g_cpts[cell * CAP + slot] = make_float2(x, y);
        g_cidx[cell * CAP + slot] = t % N;
    }
}

// ---------------- K2: match (1 thread per (i,j,n)) -------------------------
__global__ void __launch_bounds__(256)
k_match(const float* __restrict__ ps,
        const int* __restrict__ hp,
        const int* __restrict__ wp,
        int B, int N) {
    const int t    = blockIdx.x * 256 + threadIdx.x;
    const int lane = threadIdx.x & 31;
    const int total = B * B * N;

    unsigned hits[16];
    int hc = 0;

    if (t < total) {
        int n  = t % N;
        int ij = t / N;
        int i  = ij / B;
        int W = wp[0], H = hp[0];
        int s, ncx, ncy; grid_shape(W, H, s, ncx, ncy);
        float inv_c = 1.0f / (float)(1 << s);
        float sx = 0.5f * (float)(W - 1), sy = 0.5f * (float)(H - 1);

        float2 q = ((const float2*)ps)[(size_t)i * N + n];
        float x = (q.x + 1.0f) * sx, y = (q.y + 1.0f) * sy;
        int cx0 = max(0, (int)floorf((x - RAD) * inv_c));
        int cx1 = min(ncx - 1, (int)floorf((x + RAD) * inv_c));
        int cy0 = max(0, (int)floorf((y - RAD) * inv_c));
        int cy1 = min(ncy - 1, (int)floorf((y + RAD) * inv_c));

        for (int cy = cy0; cy <= cy1; cy++) {
            for (int cx = cx0; cx <= cx1; cx++) {
                int cell = ij * MAXC + cy * ncx + cx;
                int cnt = g_ccnt[cell];
                if (cnt > CAP) cnt = CAP;
                const float2* cp = g_cpts + (size_t)cell * CAP;
                const int*    ci = g_cidx + (size_t)cell * CAP;
                for (int k = 0; k < cnt; k++) {
                    float2 p = cp[k];
                    float dx = p.x - x, dy = p.y - y;
                    if (dx * dx + dy * dy <= RAD2) {
                        unsigned pk = ((unsigned)ij << 24) |
                                      ((unsigned)n << 12) | (unsigned)ci[k];
                        if (hc < 16) hits[hc++] = pk;
                        else {
                            int pos = atomicAdd(&g_npairs, 1);
                            if (pos < MAX_PAIRS) g_pairs[pos] = pk;
                        }
                    }
                }
            }
        }
    }

    // warp-aggregated append
    int pre = hc;
    #pragma unroll
    for (int o = 1; o < 32; o <<= 1) {
        int v = __shfl_up_sync(0xffffffffu, pre, o);
        if (lane >= o) pre += v;
    }
    int tot  = __shfl_sync(0xffffffffu, pre, 31);
    int excl = pre - hc;
    if (tot > 0) {
        int bpos = 0;
        if (lane == 31) bpos = atomicAdd(&g_npairs, tot);
        bpos = __shfl_sync(0xffffffffu, bpos, 31);
        for (int k = 0; k < hc; k++) {
            int pos = bpos + excl + k;
            if (pos < MAX_PAIRS) g_pairs[pos] = hits[k];
        }
    }
}

// ---------------- K3: dots + inline norms + finalize -----------------------
__global__ void __launch_bounds__(256)
k_dot(const float* __restrict__ f, float* __restrict__ out,
      int B, int N, int D) {
    __shared__ float s_red[8];
    __shared__ unsigned s_ticket;
    const int tid   = threadIdx.x;
    const int lane  = tid & 31;
    const int wid   = tid >> 5;
    const int sub   = lane >> 3;
    const int sl    = lane & 7;
    const int gw    = (blockIdx.x * 256 + tid) >> 5;
    const int nwarp = (gridDim.x * 256) >> 5;

    int np = g_npairs;
    if (np > MAX_PAIRS) np = MAX_PAIRS;
    const int D4 = D >> 2;

    float lsum = 0.f;
    for (int p0 = gw * 4; p0 < np; p0 += nwarp * 4) {
        int p = p0 + sub;
        bool valid = p < np;
        float dot = 0.f, na = 0.f, nb = 0.f;
        if (valid) {
            unsigned pk = g_pairs[p];
            int ij = pk >> 24;
            int n  = (pk >> 12) & 0xFFF;
            int m  = pk & 0xFFF;
            int i  = ij / B;
            int j  = ij - i * B;
            const float4* fa = (const float4*)(f + ((size_t)j * N + n) * D);
            const float4* fb = (const float4*)(f + ((size_t)i * N + m) * D);
            #pragma unroll 8
            for (int d = sl; d < D4; d += 8) {
                float4 a = fa[d], b = fb[d];
                dot = fmaf(a.x, b.x, fmaf(a.y, b.y, fmaf(a.z, b.z, fmaf(a.w, b.w, dot))));
                na  = fmaf(a.x, a.x, fmaf(a.y, a.y, fmaf(a.z, a.z, fmaf(a.w, a.w, na))));
                nb  = fmaf(b.x, b.x, fmaf(b.y, b.y, fmaf(b.z, b.z, fmaf(b.w, b.w, nb))));
            }
        }
        #pragma unroll
        for (int o = 1; o < 8; o <<= 1) {
            dot += __shfl_xor_sync(0xffffffffu, dot, o);
            na  += __shfl_xor_sync(0xffffffffu, na, o);
            nb  += __shfl_xor_sync(0xffffffffu, nb, o);
        }
        if (valid && sl == 0) lsum += 1.0f - dot * rsqrtf(na) * rsqrtf(nb);
    }
    // warp reduce -> block reduce -> 1 global atomic per block
    #pragma unroll
    for (int o = 16; o; o >>= 1) lsum += __shfl_xor_sync(0xffffffffu, lsum, o);
    if (lane == 0) s_red[wid] = lsum;
    __syncthreads();
    if (wid == 0) {
        float v = (lane < 8) ? s_red[lane] : 0.f;
        #pragma unroll
        for (int o = 4; o; o >>= 1) v += __shfl_xor_sync(0xffffffffu, v, o);
        if (lane == 0 && v != 0.f) atomicAdd(&g_sum, (double)v);
    }

    // distributed reset of bucket counts for next graph replay
    {
        int ncnt = B * B * MAXC;
        for (int c = blockIdx.x * 256 + tid; c < ncnt; c += gridDim.x * 256)
            g_ccnt[c] = 0;
    }

    // last-block finalize
    __threadfence();
    __syncthreads();
    if (tid == 0) s_ticket = atomicAdd(&g_done, 1u);
    __syncthreads();
    if (s_ticket == gridDim.x - 1 && tid == 0) {
        __threadfence();
        double sv = atomicAdd(&g_sum, 0.0);   // atomic read for visibility
        int c = np < 1 ? 1 : np;
        out[0] = (float)(sv / (double)c);
        g_sum = 0.0;
        g_npairs = 0;
        g_done = 0u;
    }
}

extern "C" void kernel_launch(void* const* d_in, const int* in_sizes, int n_in,
                              void* d_out, int out_size) {
    const float* features = (const float*)d_in[0];
    const float* pts_src  = (const float*)d_in[1];
    const float* pts_dst  = (const float*)d_in[2];
    const int* hp = (const int*)d_in[4];
    const int* wp = (const int*)d_in[5];
    float* out = (float*)d_out;

    int B = in_sizes[2] / in_sizes[1];
    int N = in_sizes[1] / (2 * B);
    int D = in_sizes[0] / (B * N);

    int ptBlocks = (B * B * N + 255) / 256;
    k_bin<<<ptBlocks, 256>>>(pts_dst, hp, wp, B, N);
    k_match<<<ptBlocks, 256>>>(pts_src, hp, wp, B, N);
    k_dot<<<DOT_GRID, 256>>>(features, out, B, N, D);
    (void)n_in; (void)out_size;
}